// round 15
// baseline (speedup 1.0000x reference)
#include <cuda_runtime.h>
#include <cuda_fp16.h>
#include <cstdint>

#define D 128
#define G 64
#define MAXN 50000
#define MAXE 600000
#define NEG_SLOPE 0.2f
#define CSR_NB 128
#define CSR_T 512
#define CAP 64          // bucket capacity per node (max degree ~33 for Poisson(12))

// ---------------- scratch (static __device__, no allocations) ----------------
__device__ uint2 g_Hh[(size_t)MAXN * 32];   // h = X @ W, fp16 (32 uint2 = 128 halves/row)
__device__ float g_OUT[(size_t)MAXN * D];   // layer output (fp32)
__device__ float g_as[MAXN];
__device__ float g_ad[MAXN];
__device__ int   g_deg[MAXN];
__device__ int   g_csr[(size_t)MAXN * CAP]; // bucket CSR
__device__ float g_pool[2 * G * D];
__device__ int   g_gcnt[G];
__device__ int   g_bar_count;
__device__ int   g_bar_gen;
__device__ int   g_done;                    // agg1 completion counter
__device__ unsigned short g_wth[2][128 * 128];  // bf16 hi image of W^T  [n][k]
__device__ unsigned short g_wtl[2][128 * 128];  // bf16 lo image of W^T  [n][k]

__device__ __forceinline__ float lrelu(float v) { return v > 0.f ? v : NEG_SLOPE * v; }

__device__ __forceinline__ uint32_t smem_to_u32(const void* p) {
    uint32_t a;
    asm("{ .reg .u64 t; cvta.to.shared.u64 t, %1; cvt.u32.u64 %0, t; }" : "=r"(a) : "l"(p));
    return a;
}

// round-to-nearest-even bf16 split: x = hi + lo (+ O(2^-18 x))
__device__ __forceinline__ void bfsplit(float x, uint32_t& hi16, uint32_t& lo16) {
    uint32_t u = __float_as_uint(x);
    uint32_t r = (u + 0x7fffu + ((u >> 16) & 1u)) & 0xffff0000u;
    float l = x - __uint_as_float(r);
    uint32_t ul = __float_as_uint(l);
    uint32_t rl = (ul + 0x7fffu + ((ul >> 16) & 1u)) & 0xffff0000u;
    hi16 = r >> 16; lo16 = rl >> 16;
}

__device__ __forceinline__ void ldsm_x4(uint32_t& r0, uint32_t& r1, uint32_t& r2, uint32_t& r3,
                                        uint32_t addr) {
    asm volatile("ldmatrix.sync.aligned.m8n8.x4.shared.b16 {%0,%1,%2,%3}, [%4];"
                 : "=r"(r0), "=r"(r1), "=r"(r2), "=r"(r3) : "r"(addr));
}
__device__ __forceinline__ void ldsm_x2(uint32_t& r0, uint32_t& r1, uint32_t addr) {
    asm volatile("ldmatrix.sync.aligned.m8n8.x2.shared.b16 {%0,%1}, [%2];"
                 : "=r"(r0), "=r"(r1) : "r"(addr));
}
__device__ __forceinline__ void mma_bf16(float* c, const uint32_t* a, const uint32_t* b) {
    asm volatile(
        "mma.sync.aligned.m16n8k16.row.col.f32.bf16.bf16.f32 "
        "{%0,%1,%2,%3}, {%4,%5,%6,%7}, {%8,%9}, {%0,%1,%2,%3};"
        : "+f"(c[0]), "+f"(c[1]), "+f"(c[2]), "+f"(c[3])
        : "r"(a[0]), "r"(a[1]), "r"(a[2]), "r"(a[3]), "r"(b[0]), "r"(b[1]));
}

// ---------------- software grid barrier (all CSR_NB blocks co-resident) ----------------
__device__ __forceinline__ void grid_barrier() {
    __syncthreads();
    if (threadIdx.x == 0) {
        volatile int* vgen = &g_bar_gen;
        int gen = *vgen;
        __threadfence();
        if (atomicAdd(&g_bar_count, 1) == CSR_NB - 1) {
            g_bar_count = 0;
            __threadfence();
            atomicAdd(&g_bar_gen, 1);
        } else {
            while (*vgen == gen) { __nanosleep(64); }
        }
        __threadfence();
    }
    __syncthreads();
}

// ---------------- fused CSR build: zero -> bucket scatter ----------------
__global__ void __launch_bounds__(CSR_T) k_build(const int* __restrict__ ei,
                                                 const int* __restrict__ batch, int N, int E) {
    int gid = blockIdx.x * CSR_T + threadIdx.x;
    const int total = CSR_NB * CSR_T;    // 65536 >= N

    for (int j = gid; j < N; j += total) g_deg[j] = 0;
    for (int j = gid; j < 2 * G * D; j += total) g_pool[j] = 0.f;
    if (gid < G) g_gcnt[gid] = 0;
    if (gid == 0) g_done = 0;
    grid_barrier();

    for (int n = gid; n < N; n += total) atomicAdd(&g_gcnt[batch[n]], 1);
    for (int e = gid; e < E; e += total) {
        int d = ei[E + e];
        int p = atomicAdd(&g_deg[d], 1);
        if (p < CAP) g_csr[(size_t)d * CAP + p] = ei[e];
    }
}

// ---------------- W prep (both layers) ----------------
__global__ void k_wprep(const float* __restrict__ W0, const float* __restrict__ W1) {
    int i = blockIdx.x * blockDim.x + threadIdx.x;   // 16384 threads
    if (i < 128 * 128) {
        int k = i >> 7, n = i & 127;
        uint32_t hi, lo;
        bfsplit(W0[k * 128 + n], hi, lo);
        g_wth[0][n * 128 + k] = (unsigned short)hi;
        g_wtl[0][n * 128 + k] = (unsigned short)lo;
        bfsplit(W1[k * 128 + n], hi, lo);
        g_wth[1][n * 128 + k] = (unsigned short)hi;
        g_wtl[1][n * 128 + k] = (unsigned short)lo;
    }
}

// ---------------- HMMA GEMM: H = X @ W (split-bf16, 3 products), fused dots ----------------
#define ASTR 136                              // padded bf16 row stride (272 B)
#define TILE_BYTES (128 * ASTR * 2)           // 34816
#define SM_AHI 0
#define SM_ALO TILE_BYTES
#define SM_BHI (2 * TILE_BYTES)
#define SM_BLO (3 * TILE_BYTES)
#define SMEM_GEMM_BYTES (4 * TILE_BYTES)      // 139264

__global__ void __launch_bounds__(256) k_gemm_mma(const float* __restrict__ Xext, int use_ext,
                                                  int layer,
                                                  const float* __restrict__ a_src,
                                                  const float* __restrict__ a_dst,
                                                  int rlo, int rhi) {
    extern __shared__ char smem[];
    const float* X = use_ext ? Xext : g_OUT;
    uint32_t sb = smem_to_u32(smem);
    int tid = threadIdx.x;
    int wid = tid >> 5, lane = tid & 31;
    int rbase = rlo + blockIdx.x * 128;

    // copy pre-split B images into padded smem (2048 uint4 each)
    {
        const uint4* sh = (const uint4*)g_wth[layer];
        const uint4* sl = (const uint4*)g_wtl[layer];
        for (int i = tid; i < 2048; i += 256) {
            int n = i >> 4, q = i & 15;
            uint32_t off = (uint32_t)(n * ASTR + q * 8) * 2;
            *(uint4*)(smem + SM_BHI + off) = sh[i];
            *(uint4*)(smem + SM_BLO + off) = sl[i];
        }
    }

    // load + split-convert A: 128 rows x 16 chunks of 8 floats
#pragma unroll
    for (int it = 0; it < 8; it++) {
        int idx = it * 256 + tid;            // 0..2047
        int r = idx >> 4, c = idx & 15;
        float4 f0 = make_float4(0.f, 0.f, 0.f, 0.f), f1 = f0;
        int row = rbase + r;
        if (row < rhi) {
            const float4* xp = (const float4*)(X + (size_t)row * 128 + c * 8);
            f0 = xp[0]; f1 = xp[1];
        }
        float v[8] = {f0.x, f0.y, f0.z, f0.w, f1.x, f1.y, f1.z, f1.w};
        uint32_t hp[4], lp[4];
#pragma unroll
        for (int q = 0; q < 4; q++) {
            uint32_t h0, l0, h1, l1;
            bfsplit(v[2 * q], h0, l0);
            bfsplit(v[2 * q + 1], h1, l1);
            hp[q] = h0 | (h1 << 16);
            lp[q] = l0 | (l1 << 16);
        }
        uint32_t off = (uint32_t)(r * ASTR + c * 8) * 2;
        *(uint4*)(smem + SM_AHI + off) = make_uint4(hp[0], hp[1], hp[2], hp[3]);
        *(uint4*)(smem + SM_ALO + off) = make_uint4(lp[0], lp[1], lp[2], lp[3]);
    }
    __syncthreads();

    int wm = wid >> 2, wn = wid & 3;        // 2 x 4 warp grid
    int m0w = wm * 64, n0w = wn * 32;

    float acc[4][4][4];
#pragma unroll
    for (int i = 0; i < 4; i++)
#pragma unroll
        for (int j = 0; j < 4; j++)
#pragma unroll
            for (int q = 0; q < 4; q++) acc[i][j][q] = 0.f;

    int a_row_in = lane & 15;
    int a_col_in = (lane >> 4) * 8;
    int b_row_in = lane & 7;
    int b_col_in = ((lane >> 3) & 1) * 8;

#pragma unroll
    for (int prod = 0; prod < 3; prod++) {
        uint32_t abase = sb + ((prod == 2) ? SM_ALO : SM_AHI);
        uint32_t bbase = sb + ((prod == 1) ? SM_BLO : SM_BHI);
#pragma unroll
        for (int ks = 0; ks < 8; ks++) {
            int k0 = ks * 16;
            uint32_t a[4][4], b[4][2];
#pragma unroll
            for (int mt = 0; mt < 4; mt++) {
                uint32_t ad = abase +
                    (uint32_t)((m0w + mt * 16 + a_row_in) * ASTR + k0 + a_col_in) * 2;
                ldsm_x4(a[mt][0], a[mt][1], a[mt][2], a[mt][3], ad);
            }
#pragma unroll
            for (int nt = 0; nt < 4; nt++) {
                uint32_t bd = bbase +
                    (uint32_t)((n0w + nt * 8 + b_row_in) * ASTR + k0 + b_col_in) * 2;
                ldsm_x2(b[nt][0], b[nt][1], bd);
            }
#pragma unroll
            for (int mt = 0; mt < 4; mt++)
#pragma unroll
                for (int nt = 0; nt < 4; nt++)
                    mma_bf16(acc[mt][nt], a[mt], b[nt]);
        }
    }

    // epilogue: store H (fp16) + per-lane partial attention dots (fp32)
    int g = lane >> 2, t = lane & 3;
    float vs0[4] = {0, 0, 0, 0}, vs1[4] = {0, 0, 0, 0};
    float vd0[4] = {0, 0, 0, 0}, vd1[4] = {0, 0, 0, 0};
#pragma unroll
    for (int nt = 0; nt < 4; nt++) {
        int col = n0w + nt * 8 + 2 * t;
        float s0 = __ldg(a_src + col), s1 = __ldg(a_src + col + 1);
        float d0 = __ldg(a_dst + col), d1 = __ldg(a_dst + col + 1);
#pragma unroll
        for (int mt = 0; mt < 4; mt++) {
            vs0[mt] += acc[mt][nt][0] * s0 + acc[mt][nt][1] * s1;
            vs1[mt] += acc[mt][nt][2] * s0 + acc[mt][nt][3] * s1;
            vd0[mt] += acc[mt][nt][0] * d0 + acc[mt][nt][1] * d1;
            vd1[mt] += acc[mt][nt][2] * d0 + acc[mt][nt][3] * d1;
        }
    }
    uint32_t* Hu = (uint32_t*)g_Hh;             // 64 uints per row
#pragma unroll
    for (int mt = 0; mt < 4; mt++) {
        int r0 = rbase + m0w + mt * 16 + g;
        int r1 = r0 + 8;
#pragma unroll
        for (int nt = 0; nt < 4; nt++) {
            int col = n0w + nt * 8 + 2 * t;
            if (r0 < rhi) {
                __half2 h01 = __floats2half2_rn(acc[mt][nt][0], acc[mt][nt][1]);
                Hu[(size_t)r0 * 64 + (col >> 1)] = *(uint32_t*)&h01;
            }
            if (r1 < rhi) {
                __half2 h23 = __floats2half2_rn(acc[mt][nt][2], acc[mt][nt][3]);
                Hu[(size_t)r1 * 64 + (col >> 1)] = *(uint32_t*)&h23;
            }
        }
    }

    // reduce dots: butterfly over t lanes, then smem atomics across warps
#pragma unroll
    for (int mt = 0; mt < 4; mt++) {
#pragma unroll
        for (int off = 1; off < 4; off <<= 1) {
            vs0[mt] += __shfl_xor_sync(0xffffffffu, vs0[mt], off);
            vs1[mt] += __shfl_xor_sync(0xffffffffu, vs1[mt], off);
            vd0[mt] += __shfl_xor_sync(0xffffffffu, vd0[mt], off);
            vd1[mt] += __shfl_xor_sync(0xffffffffu, vd1[mt], off);
        }
    }
    __syncthreads();                           // all warps done with As/Bs smem
    float* svs = (float*)smem;
    float* svd = (float*)(smem + 512);
    if (tid < 128) { svs[tid] = 0.f; svd[tid] = 0.f; }
    __syncthreads();
    if (t == 0) {
#pragma unroll
        for (int mt = 0; mt < 4; mt++) {
            int rl = m0w + mt * 16 + g;
            atomicAdd(&svs[rl], vs0[mt]);
            atomicAdd(&svd[rl], vd0[mt]);
            atomicAdd(&svs[rl + 8], vs1[mt]);
            atomicAdd(&svd[rl + 8], vd1[mt]);
        }
    }
    __syncthreads();
    if (tid < 128) {
        int row = rbase + tid;
        if (row < rhi) { g_as[row] = svs[tid]; g_ad[row] = svd[tid]; }
    }
}

// ---------------- GAT aggregation: lane-parallel weights + shfl broadcast ----------------
// Layer-1 full call also finalizes the output (last-block-done pattern).
__global__ void __launch_bounds__(256, 6) k_agg(const float* __restrict__ bias,
                                                const int* __restrict__ batch,
                                                int nodeBegin, int nodeEnd,
                                                int do_relu, int layer,
                                                int do_final, int nblocks,
                                                float* __restrict__ out) {
    const unsigned M = 0xffffffffu;
    int wid = threadIdx.x >> 5, lane = threadIdx.x & 31;
    int w = nodeBegin + blockIdx.x * 8 + wid;
    bool valid = (w < nodeEnd);

    float4 o = make_float4(0.f, 0.f, 0.f, 0.f);
    if (valid) {
        float adi = g_ad[w];
        float exs = __expf(lrelu(g_as[w] + adi));   // self loop
        int deg = min(__ldg(&g_deg[w]), CAP);
        int base = w * CAP;

        uint2 hw = g_Hh[(size_t)w * 32 + lane];
        float2 f0 = __half22float2(*(__half2*)&hw.x), f1 = __half22float2(*(__half2*)&hw.y);
        float dpart = 0.f;
        float ax = exs * f0.x, ay = exs * f0.y, az = exs * f1.x, aw = exs * f1.y;

        for (int c0 = 0; c0 < deg; c0 += 32) {
            int cnt = min(32, deg - c0);
            int s = 0; float ex = 0.f;
            if (lane < cnt) {
                s = __ldg(&g_csr[base + c0 + lane]);
                ex = __expf(lrelu(__ldg(&g_as[s]) + adi));
            }
            dpart += ex;

            int j = 0;
            for (; j + 4 <= cnt; j += 4) {
                int s0 = __shfl_sync(M, s, j),     s1 = __shfl_sync(M, s, j + 1);
                int s2 = __shfl_sync(M, s, j + 2), s3 = __shfl_sync(M, s, j + 3);
                float e0 = __shfl_sync(M, ex, j),     e1 = __shfl_sync(M, ex, j + 1);
                float e2 = __shfl_sync(M, ex, j + 2), e3 = __shfl_sync(M, ex, j + 3);
                uint2 h0 = g_Hh[(size_t)s0 * 32 + lane];
                uint2 h1 = g_Hh[(size_t)s1 * 32 + lane];
                uint2 h2 = g_Hh[(size_t)s2 * 32 + lane];
                uint2 h3 = g_Hh[(size_t)s3 * 32 + lane];
                float2 a0 = __half22float2(*(__half2*)&h0.x), b0 = __half22float2(*(__half2*)&h0.y);
                float2 a1 = __half22float2(*(__half2*)&h1.x), b1 = __half22float2(*(__half2*)&h1.y);
                float2 a2 = __half22float2(*(__half2*)&h2.x), b2 = __half22float2(*(__half2*)&h2.y);
                float2 a3 = __half22float2(*(__half2*)&h3.x), b3 = __half22float2(*(__half2*)&h3.y);
                ax += e0 * a0.x + e1 * a1.x + e2 * a2.x + e3 * a3.x;
                ay += e0 * a0.y + e1 * a1.y + e2 * a2.y + e3 * a3.y;
                az += e0 * b0.x + e1 * b1.x + e2 * b2.x + e3 * b3.x;
                aw += e0 * b0.y + e1 * b1.y + e2 * b2.y + e3 * b3.y;
            }
            for (; j < cnt; j++) {
                int sj = __shfl_sync(M, s, j);
                float ej = __shfl_sync(M, ex, j);
                uint2 hj = g_Hh[(size_t)sj * 32 + lane];
                float2 g0 = __half22float2(*(__half2*)&hj.x), g1 = __half22float2(*(__half2*)&hj.y);
                ax += ej * g0.x; ay += ej * g0.y; az += ej * g1.x; aw += ej * g1.y;
            }
        }

        float dsum = dpart;
#pragma unroll
        for (int off = 16; off > 0; off >>= 1) dsum += __shfl_xor_sync(M, dsum, off);
        dsum += exs;

        float inv = 1.f / dsum;
        float4 bv = *(const float4*)(bias + lane * 4);
        o.x = ax * inv + bv.x;
        o.y = ay * inv + bv.y;
        o.z = az * inv + bv.z;
        o.w = aw * inv + bv.w;
        if (do_relu) {
            o.x = fmaxf(o.x, 0.f); o.y = fmaxf(o.y, 0.f);
            o.z = fmaxf(o.z, 0.f); o.w = fmaxf(o.w, 0.f);
        }
        ((float4*)g_OUT)[(size_t)w * 32 + lane] = o;
    }

    // fused mean-pool accumulation (batch sorted -> most blocks single-graph)
    __shared__ float sp[8][128];
    sp[wid][lane * 4 + 0] = o.x;
    sp[wid][lane * 4 + 1] = o.y;
    sp[wid][lane * 4 + 2] = o.z;
    sp[wid][lane * 4 + 3] = o.w;
    __syncthreads();

    float* pool = g_pool + layer * G * D;
    int nfirst = nodeBegin + blockIdx.x * 8;
    int nlast = min(nfirst + 7, nodeEnd - 1);
    int b0 = batch[nfirst], b1 = batch[nlast];
    int tid = threadIdx.x;
    if (b0 == b1) {
        if (tid < 128) {
            float s = 0.f;
#pragma unroll
            for (int r = 0; r < 8; r++) s += sp[r][tid];
            atomicAdd(&pool[b0 * 128 + tid], s);
        }
    } else {
        if (tid < 128) {
#pragma unroll
            for (int r = 0; r < 8; r++) {
                int node = nfirst + r;
                if (node < nodeEnd) atomicAdd(&pool[batch[node] * 128 + tid], sp[r][tid]);
            }
        }
    }

    // last-block-done finalization (layer-1 full call only)
    if (do_final) {
        __threadfence();
        __shared__ int slast;
        if (tid == 0) slast = (atomicAdd(&g_done, 1) == nblocks - 1) ? 1 : 0;
        __syncthreads();
        if (slast) {
            for (int i = tid; i < 2 * G * D; i += 256) {
                int gg = (i >> 7) & (G - 1);
                out[i] = g_pool[i] / (float)max(g_gcnt[gg], 1);
            }
        }
    }
}

// ---------------- launch (capture-forked two-stream pipelined graph, 7 nodes) ----------------
extern "C" void kernel_launch(void* const* d_in, const int* in_sizes, int n_in,
                              void* d_out, int out_size) {
    const float* x      = (const float*)d_in[0];
    const int*   ei     = (const int*)d_in[1];
    const int*   batch  = (const int*)d_in[3];
    const float* W0     = (const float*)d_in[4];
    const float* a_src0 = (const float*)d_in[5];
    const float* a_dst0 = (const float*)d_in[6];
    const float* b0     = (const float*)d_in[7];
    const float* W1     = (const float*)d_in[8];
    const float* a_src1 = (const float*)d_in[9];
    const float* a_dst1 = (const float*)d_in[10];
    const float* b1     = (const float*)d_in[11];
    float* out = (float*)d_out;

    int N = in_sizes[0] / D;
    int E = in_sizes[1] / 2;
    if (N > MAXN) N = MAXN;
    if (E > MAXE) E = MAXE;

    int Nh = (N / 2) & ~127;
    if (Nh <= 0) Nh = N;
    int gemmBlocks = (N + 127) / 128;
    int loTiles = Nh / 128;
    int hiTiles = (N - Nh + 127) / 128;
    int loAgg = (Nh + 7) / 8;
    int hiAgg = (N - Nh + 7) / 8;
    int fullAgg = (N + 7) / 8;

    cudaFuncSetAttribute(k_gemm_mma, cudaFuncAttributeMaxDynamicSharedMemorySize, SMEM_GEMM_BYTES);

    static cudaStream_t s2 = nullptr;
    static cudaEvent_t evRoot = nullptr, evCSR = nullptr, evG0 = nullptr, evHi = nullptr;
    if (s2 == nullptr) {
        cudaStreamCreateWithFlags(&s2, cudaStreamNonBlocking);
        cudaEventCreateWithFlags(&evRoot, cudaEventDisableTiming);
        cudaEventCreateWithFlags(&evCSR, cudaEventDisableTiming);
        cudaEventCreateWithFlags(&evG0, cudaEventDisableTiming);
        cudaEventCreateWithFlags(&evHi, cudaEventDisableTiming);
    }

    // fork
    cudaEventRecord(evRoot, 0);
    cudaStreamWaitEvent(s2, evRoot, 0);

    // branch B on s2: fused bucket-CSR build
    k_build<<<CSR_NB, CSR_T, 0, s2>>>(ei, batch, N, E);
    cudaEventRecord(evCSR, s2);

    // branch A on main: W prep + full layer-0 GEMM (fused attention dots)
    k_wprep<<<64, 256>>>(W0, W1);
    k_gemm_mma<<<gemmBlocks, 256, SMEM_GEMM_BYTES>>>(x, 1, 0, a_src0, a_dst0, 0, N);
    cudaEventRecord(evG0, 0);

    // joins for the pipelined middle section
    cudaStreamWaitEvent(0, evCSR, 0);
    cudaStreamWaitEvent(s2, evG0, 0);

    // pipelined halves: agg0 -> gemm1 per node range
    k_agg<<<loAgg, 256>>>(b0, batch, 0, Nh, 1, 0, 0, 0, nullptr);
    if (hiAgg > 0) k_agg<<<hiAgg, 256, 0, s2>>>(b0, batch, Nh, N, 1, 0, 0, 0, nullptr);
    k_gemm_mma<<<loTiles, 256, SMEM_GEMM_BYTES>>>(nullptr, 0, 1, a_src1, a_dst1, 0, Nh);
    if (hiTiles > 0)
        k_gemm_mma<<<hiTiles, 256, SMEM_GEMM_BYTES, s2>>>(nullptr, 0, 1, a_src1, a_dst1, Nh, N);
    cudaEventRecord(evHi, s2);
    cudaStreamWaitEvent(0, evHi, 0);

    // layer-1 aggregation (full) + fused final division (last block)
    k_agg<<<fullAgg, 256>>>(b1, batch, 0, N, 0, 1, 1, fullAgg, out);
}

// round 16
// speedup vs baseline: 1.1915x; 1.1915x over previous
#include <cuda_runtime.h>
#include <cuda_fp16.h>
#include <cstdint>

#define D 128
#define G 64
#define MAXN 50000
#define MAXE 600000
#define NEG_SLOPE 0.2f
#define CSR_NB 128
#define CSR_T 512
#define CAP 64          // bucket capacity per node (max degree ~33 for Poisson(12))

// ---------------- scratch (static __device__, no allocations) ----------------
__device__ uint2 g_Hh[(size_t)MAXN * 32];   // h = X @ W, fp16 (32 uint2 = 128 halves/row)
__device__ float g_OUT[(size_t)MAXN * D];   // layer output (fp32)
__device__ float g_as[MAXN];
__device__ float g_ad[MAXN];
__device__ int   g_deg[MAXN];
__device__ int   g_csr[(size_t)MAXN * CAP]; // bucket CSR
__device__ float g_pool[2 * G * D];
__device__ int   g_gcnt[G];
__device__ int   g_bar_count;
__device__ int   g_bar_gen;
__device__ unsigned short g_wth[2][128 * 128];  // bf16 hi image of W^T  [n][k]
__device__ unsigned short g_wtl[2][128 * 128];  // bf16 lo image of W^T  [n][k]

__device__ __forceinline__ float lrelu(float v) { return v > 0.f ? v : NEG_SLOPE * v; }

__device__ __forceinline__ uint32_t smem_to_u32(const void* p) {
    uint32_t a;
    asm("{ .reg .u64 t; cvta.to.shared.u64 t, %1; cvt.u32.u64 %0, t; }" : "=r"(a) : "l"(p));
    return a;
}

// round-to-nearest-even bf16 split: x = hi + lo (+ O(2^-18 x))
__device__ __forceinline__ void bfsplit(float x, uint32_t& hi16, uint32_t& lo16) {
    uint32_t u = __float_as_uint(x);
    uint32_t r = (u + 0x7fffu + ((u >> 16) & 1u)) & 0xffff0000u;
    float l = x - __uint_as_float(r);
    uint32_t ul = __float_as_uint(l);
    uint32_t rl = (ul + 0x7fffu + ((ul >> 16) & 1u)) & 0xffff0000u;
    hi16 = r >> 16; lo16 = rl >> 16;
}

__device__ __forceinline__ void ldsm_x4(uint32_t& r0, uint32_t& r1, uint32_t& r2, uint32_t& r3,
                                        uint32_t addr) {
    asm volatile("ldmatrix.sync.aligned.m8n8.x4.shared.b16 {%0,%1,%2,%3}, [%4];"
                 : "=r"(r0), "=r"(r1), "=r"(r2), "=r"(r3) : "r"(addr));
}
__device__ __forceinline__ void ldsm_x2(uint32_t& r0, uint32_t& r1, uint32_t addr) {
    asm volatile("ldmatrix.sync.aligned.m8n8.x2.shared.b16 {%0,%1}, [%2];"
                 : "=r"(r0), "=r"(r1) : "r"(addr));
}
__device__ __forceinline__ void mma_bf16(float* c, const uint32_t* a, const uint32_t* b) {
    asm volatile(
        "mma.sync.aligned.m16n8k16.row.col.f32.bf16.bf16.f32 "
        "{%0,%1,%2,%3}, {%4,%5,%6,%7}, {%8,%9}, {%0,%1,%2,%3};"
        : "+f"(c[0]), "+f"(c[1]), "+f"(c[2]), "+f"(c[3])
        : "r"(a[0]), "r"(a[1]), "r"(a[2]), "r"(a[3]), "r"(b[0]), "r"(b[1]));
}

// ---------------- software grid barrier (all CSR_NB blocks co-resident) ----------------
__device__ __forceinline__ void grid_barrier() {
    __syncthreads();
    if (threadIdx.x == 0) {
        volatile int* vgen = &g_bar_gen;
        int gen = *vgen;
        __threadfence();
        if (atomicAdd(&g_bar_count, 1) == CSR_NB - 1) {
            g_bar_count = 0;
            __threadfence();
            atomicAdd(&g_bar_gen, 1);
        } else {
            while (*vgen == gen) { __nanosleep(64); }
        }
        __threadfence();
    }
    __syncthreads();
}

// ---------------- fused CSR build: zero -> bucket scatter (no scan needed) ----------------
__global__ void __launch_bounds__(CSR_T) k_build(const int* __restrict__ ei,
                                                 const int* __restrict__ batch, int N, int E) {
    int gid = blockIdx.x * CSR_T + threadIdx.x;
    const int total = CSR_NB * CSR_T;    // 65536 >= N

    for (int j = gid; j < N; j += total) g_deg[j] = 0;
    for (int j = gid; j < 2 * G * D; j += total) g_pool[j] = 0.f;
    if (gid < G) g_gcnt[gid] = 0;
    grid_barrier();

    for (int n = gid; n < N; n += total) atomicAdd(&g_gcnt[batch[n]], 1);
    for (int e = gid; e < E; e += total) {
        int d = ei[E + e];
        int p = atomicAdd(&g_deg[d], 1);
        if (p < CAP) g_csr[(size_t)d * CAP + p] = ei[e];
    }
}

// ---------------- W prep (both layers) ----------------
__global__ void k_wprep(const float* __restrict__ W0, const float* __restrict__ W1) {
    int i = blockIdx.x * blockDim.x + threadIdx.x;   // 16384 threads
    if (i < 128 * 128) {
        int k = i >> 7, n = i & 127;
        uint32_t hi, lo;
        bfsplit(W0[k * 128 + n], hi, lo);
        g_wth[0][n * 128 + k] = (unsigned short)hi;
        g_wtl[0][n * 128 + k] = (unsigned short)lo;
        bfsplit(W1[k * 128 + n], hi, lo);
        g_wth[1][n * 128 + k] = (unsigned short)hi;
        g_wtl[1][n * 128 + k] = (unsigned short)lo;
    }
}

// ---------------- HMMA GEMM: H = X @ W (split-bf16, 3 products), fused dots ----------------
#define ASTR 136                              // padded bf16 row stride (272 B)
#define TILE_BYTES (128 * ASTR * 2)           // 34816
#define SM_AHI 0
#define SM_ALO TILE_BYTES
#define SM_BHI (2 * TILE_BYTES)
#define SM_BLO (3 * TILE_BYTES)
#define SMEM_GEMM_BYTES (4 * TILE_BYTES)      // 139264

__global__ void __launch_bounds__(256) k_gemm_mma(const float* __restrict__ Xext, int use_ext,
                                                  int layer,
                                                  const float* __restrict__ a_src,
                                                  const float* __restrict__ a_dst,
                                                  int rlo, int rhi) {
    extern __shared__ char smem[];
    const float* X = use_ext ? Xext : g_OUT;
    uint32_t sb = smem_to_u32(smem);
    int tid = threadIdx.x;
    int wid = tid >> 5, lane = tid & 31;
    int rbase = rlo + blockIdx.x * 128;

    // copy pre-split B images into padded smem (2048 uint4 each)
    {
        const uint4* sh = (const uint4*)g_wth[layer];
        const uint4* sl = (const uint4*)g_wtl[layer];
        for (int i = tid; i < 2048; i += 256) {
            int n = i >> 4, q = i & 15;
            uint32_t off = (uint32_t)(n * ASTR + q * 8) * 2;
            *(uint4*)(smem + SM_BHI + off) = sh[i];
            *(uint4*)(smem + SM_BLO + off) = sl[i];
        }
    }

    // load + split-convert A: 128 rows x 16 chunks of 8 floats
#pragma unroll
    for (int it = 0; it < 8; it++) {
        int idx = it * 256 + tid;            // 0..2047
        int r = idx >> 4, c = idx & 15;
        float4 f0 = make_float4(0.f, 0.f, 0.f, 0.f), f1 = f0;
        int row = rbase + r;
        if (row < rhi) {
            const float4* xp = (const float4*)(X + (size_t)row * 128 + c * 8);
            f0 = xp[0]; f1 = xp[1];
        }
        float v[8] = {f0.x, f0.y, f0.z, f0.w, f1.x, f1.y, f1.z, f1.w};
        uint32_t hp[4], lp[4];
#pragma unroll
        for (int q = 0; q < 4; q++) {
            uint32_t h0, l0, h1, l1;
            bfsplit(v[2 * q], h0, l0);
            bfsplit(v[2 * q + 1], h1, l1);
            hp[q] = h0 | (h1 << 16);
            lp[q] = l0 | (l1 << 16);
        }
        uint32_t off = (uint32_t)(r * ASTR + c * 8) * 2;
        *(uint4*)(smem + SM_AHI + off) = make_uint4(hp[0], hp[1], hp[2], hp[3]);
        *(uint4*)(smem + SM_ALO + off) = make_uint4(lp[0], lp[1], lp[2], lp[3]);
    }
    __syncthreads();

    int wm = wid >> 2, wn = wid & 3;        // 2 x 4 warp grid
    int m0w = wm * 64, n0w = wn * 32;

    float acc[4][4][4];
#pragma unroll
    for (int i = 0; i < 4; i++)
#pragma unroll
        for (int j = 0; j < 4; j++)
#pragma unroll
            for (int q = 0; q < 4; q++) acc[i][j][q] = 0.f;

    int a_row_in = lane & 15;
    int a_col_in = (lane >> 4) * 8;
    int b_row_in = lane & 7;
    int b_col_in = ((lane >> 3) & 1) * 8;

#pragma unroll
    for (int prod = 0; prod < 3; prod++) {
        uint32_t abase = sb + ((prod == 2) ? SM_ALO : SM_AHI);
        uint32_t bbase = sb + ((prod == 1) ? SM_BLO : SM_BHI);
#pragma unroll
        for (int ks = 0; ks < 8; ks++) {
            int k0 = ks * 16;
            uint32_t a[4][4], b[4][2];
#pragma unroll
            for (int mt = 0; mt < 4; mt++) {
                uint32_t ad = abase +
                    (uint32_t)((m0w + mt * 16 + a_row_in) * ASTR + k0 + a_col_in) * 2;
                ldsm_x4(a[mt][0], a[mt][1], a[mt][2], a[mt][3], ad);
            }
#pragma unroll
            for (int nt = 0; nt < 4; nt++) {
                uint32_t bd = bbase +
                    (uint32_t)((n0w + nt * 8 + b_row_in) * ASTR + k0 + b_col_in) * 2;
                ldsm_x2(b[nt][0], b[nt][1], bd);
            }
#pragma unroll
            for (int mt = 0; mt < 4; mt++)
#pragma unroll
                for (int nt = 0; nt < 4; nt++)
                    mma_bf16(acc[mt][nt], a[mt], b[nt]);
        }
    }

    // epilogue: store H (fp16) + per-lane partial attention dots (fp32)
    int g = lane >> 2, t = lane & 3;
    float vs0[4] = {0, 0, 0, 0}, vs1[4] = {0, 0, 0, 0};
    float vd0[4] = {0, 0, 0, 0}, vd1[4] = {0, 0, 0, 0};
#pragma unroll
    for (int nt = 0; nt < 4; nt++) {
        int col = n0w + nt * 8 + 2 * t;
        float s0 = __ldg(a_src + col), s1 = __ldg(a_src + col + 1);
        float d0 = __ldg(a_dst + col), d1 = __ldg(a_dst + col + 1);
#pragma unroll
        for (int mt = 0; mt < 4; mt++) {
            vs0[mt] += acc[mt][nt][0] * s0 + acc[mt][nt][1] * s1;
            vs1[mt] += acc[mt][nt][2] * s0 + acc[mt][nt][3] * s1;
            vd0[mt] += acc[mt][nt][0] * d0 + acc[mt][nt][1] * d1;
            vd1[mt] += acc[mt][nt][2] * d0 + acc[mt][nt][3] * d1;
        }
    }
    uint32_t* Hu = (uint32_t*)g_Hh;             // 64 uints per row
#pragma unroll
    for (int mt = 0; mt < 4; mt++) {
        int r0 = rbase + m0w + mt * 16 + g;
        int r1 = r0 + 8;
#pragma unroll
        for (int nt = 0; nt < 4; nt++) {
            int col = n0w + nt * 8 + 2 * t;
            if (r0 < rhi) {
                __half2 h01 = __floats2half2_rn(acc[mt][nt][0], acc[mt][nt][1]);
                Hu[(size_t)r0 * 64 + (col >> 1)] = *(uint32_t*)&h01;
            }
            if (r1 < rhi) {
                __half2 h23 = __floats2half2_rn(acc[mt][nt][2], acc[mt][nt][3]);
                Hu[(size_t)r1 * 64 + (col >> 1)] = *(uint32_t*)&h23;
            }
        }
    }

    // reduce dots: butterfly over t lanes, then smem atomics across warps
#pragma unroll
    for (int mt = 0; mt < 4; mt++) {
#pragma unroll
        for (int off = 1; off < 4; off <<= 1) {
            vs0[mt] += __shfl_xor_sync(0xffffffffu, vs0[mt], off);
            vs1[mt] += __shfl_xor_sync(0xffffffffu, vs1[mt], off);
            vd0[mt] += __shfl_xor_sync(0xffffffffu, vd0[mt], off);
            vd1[mt] += __shfl_xor_sync(0xffffffffu, vd1[mt], off);
        }
    }
    __syncthreads();                           // all warps done with As/Bs smem
    float* svs = (float*)smem;
    float* svd = (float*)(smem + 512);
    if (tid < 128) { svs[tid] = 0.f; svd[tid] = 0.f; }
    __syncthreads();
    if (t == 0) {
#pragma unroll
        for (int mt = 0; mt < 4; mt++) {
            int rl = m0w + mt * 16 + g;
            atomicAdd(&svs[rl], vs0[mt]);
            atomicAdd(&svd[rl], vd0[mt]);
            atomicAdd(&svs[rl + 8], vs1[mt]);
            atomicAdd(&svd[rl + 8], vd1[mt]);
        }
    }
    __syncthreads();
    if (tid < 128) {
        int row = rbase + tid;
        if (row < rhi) { g_as[row] = svs[tid]; g_ad[row] = svd[tid]; }
    }
}

// ---------------- GAT aggregation: lane-parallel weights + shfl broadcast ----------------
__global__ void __launch_bounds__(256) k_agg(const float* __restrict__ bias,
                                             const int* __restrict__ batch,
                                             int nodeBegin, int nodeEnd,
                                             int do_relu, int layer, int do_out) {
    const unsigned M = 0xffffffffu;
    int wid = threadIdx.x >> 5, lane = threadIdx.x & 31;
    int w = nodeBegin + blockIdx.x * 8 + wid;
    bool valid = (w < nodeEnd);

    float4 o = make_float4(0.f, 0.f, 0.f, 0.f);
    if (valid) {
        float adi = g_ad[w];
        float exs = __expf(lrelu(g_as[w] + adi));   // self loop
        int deg = min(__ldg(&g_deg[w]), CAP);
        int base = w * CAP;

        uint2 hw = g_Hh[(size_t)w * 32 + lane];
        float2 f0 = __half22float2(*(__half2*)&hw.x), f1 = __half22float2(*(__half2*)&hw.y);
        float dpart = 0.f;
        float ax = exs * f0.x, ay = exs * f0.y, az = exs * f1.x, aw = exs * f1.y;

        for (int c0 = 0; c0 < deg; c0 += 32) {
            int cnt = min(32, deg - c0);
            int s = 0; float ex = 0.f;
            if (lane < cnt) {
                s = __ldg(&g_csr[base + c0 + lane]);
                ex = __expf(lrelu(__ldg(&g_as[s]) + adi));
            }
            dpart += ex;

            int j = 0;
            for (; j + 4 <= cnt; j += 4) {
                int s0 = __shfl_sync(M, s, j),     s1 = __shfl_sync(M, s, j + 1);
                int s2 = __shfl_sync(M, s, j + 2), s3 = __shfl_sync(M, s, j + 3);
                float e0 = __shfl_sync(M, ex, j),     e1 = __shfl_sync(M, ex, j + 1);
                float e2 = __shfl_sync(M, ex, j + 2), e3 = __shfl_sync(M, ex, j + 3);
                uint2 h0 = g_Hh[(size_t)s0 * 32 + lane];
                uint2 h1 = g_Hh[(size_t)s1 * 32 + lane];
                uint2 h2 = g_Hh[(size_t)s2 * 32 + lane];
                uint2 h3 = g_Hh[(size_t)s3 * 32 + lane];
                float2 a0 = __half22float2(*(__half2*)&h0.x), b0 = __half22float2(*(__half2*)&h0.y);
                float2 a1 = __half22float2(*(__half2*)&h1.x), b1 = __half22float2(*(__half2*)&h1.y);
                float2 a2 = __half22float2(*(__half2*)&h2.x), b2 = __half22float2(*(__half2*)&h2.y);
                float2 a3 = __half22float2(*(__half2*)&h3.x), b3 = __half22float2(*(__half2*)&h3.y);
                ax += e0 * a0.x + e1 * a1.x + e2 * a2.x + e3 * a3.x;
                ay += e0 * a0.y + e1 * a1.y + e2 * a2.y + e3 * a3.y;
                az += e0 * b0.x + e1 * b1.x + e2 * b2.x + e3 * b3.x;
                aw += e0 * b0.y + e1 * b1.y + e2 * b2.y + e3 * b3.y;
            }
            for (; j < cnt; j++) {
                int sj = __shfl_sync(M, s, j);
                float ej = __shfl_sync(M, ex, j);
                uint2 hj = g_Hh[(size_t)sj * 32 + lane];
                float2 g0 = __half22float2(*(__half2*)&hj.x), g1 = __half22float2(*(__half2*)&hj.y);
                ax += ej * g0.x; ay += ej * g0.y; az += ej * g1.x; aw += ej * g1.y;
            }
        }

        float dsum = dpart;
#pragma unroll
        for (int off = 16; off > 0; off >>= 1) dsum += __shfl_xor_sync(M, dsum, off);
        dsum += exs;

        float inv = 1.f / dsum;
        float4 bv = *(const float4*)(bias + lane * 4);
        o.x = ax * inv + bv.x;
        o.y = ay * inv + bv.y;
        o.z = az * inv + bv.z;
        o.w = aw * inv + bv.w;
        if (do_relu) {
            o.x = fmaxf(o.x, 0.f); o.y = fmaxf(o.y, 0.f);
            o.z = fmaxf(o.z, 0.f); o.w = fmaxf(o.w, 0.f);
        }
        if (do_out) ((float4*)g_OUT)[(size_t)w * 32 + lane] = o;   // dead for layer 1
    }

    // fused mean-pool accumulation (batch sorted -> most blocks single-graph)
    __shared__ float sp[8][128];
    sp[wid][lane * 4 + 0] = o.x;
    sp[wid][lane * 4 + 1] = o.y;
    sp[wid][lane * 4 + 2] = o.z;
    sp[wid][lane * 4 + 3] = o.w;
    __syncthreads();

    float* pool = g_pool + layer * G * D;
    int nfirst = nodeBegin + blockIdx.x * 8;
    int nlast = min(nfirst + 7, nodeEnd - 1);
    int b0 = batch[nfirst], b1 = batch[nlast];
    int tid = threadIdx.x;
    if (b0 == b1) {
        if (tid < 128) {
            float s = 0.f;
#pragma unroll
            for (int r = 0; r < 8; r++) s += sp[r][tid];
            atomicAdd(&pool[b0 * 128 + tid], s);
        }
    } else {
        if (tid < 128) {
#pragma unroll
            for (int r = 0; r < 8; r++) {
                int node = nfirst + r;
                if (node < nodeEnd) atomicAdd(&pool[batch[node] * 128 + tid], sp[r][tid]);
            }
        }
    }
}

__global__ void k_final(float* __restrict__ out) {
    int i = blockIdx.x * blockDim.x + threadIdx.x;
    if (i >= 2 * G * D) return;
    int g = (i >> 7) & (G - 1);
    float c = (float)max(g_gcnt[g], 1);
    out[i] = g_pool[i] / c;
}

// ---------------- launch (capture-forked two-stream pipelined graph) ----------------
extern "C" void kernel_launch(void* const* d_in, const int* in_sizes, int n_in,
                              void* d_out, int out_size) {
    const float* x      = (const float*)d_in[0];
    const int*   ei     = (const int*)d_in[1];
    const int*   batch  = (const int*)d_in[3];
    const float* W0     = (const float*)d_in[4];
    const float* a_src0 = (const float*)d_in[5];
    const float* a_dst0 = (const float*)d_in[6];
    const float* b0     = (const float*)d_in[7];
    const float* W1     = (const float*)d_in[8];
    const float* a_src1 = (const float*)d_in[9];
    const float* a_dst1 = (const float*)d_in[10];
    const float* b1     = (const float*)d_in[11];
    float* out = (float*)d_out;

    int N = in_sizes[0] / D;
    int E = in_sizes[1] / 2;
    if (N > MAXN) N = MAXN;
    if (E > MAXE) E = MAXE;

    int Nh = (N / 2) & ~127;
    if (Nh <= 0) Nh = N;
    int gemmBlocks = (N + 127) / 128;
    int loTiles = Nh / 128;
    int hiTiles = (N - Nh + 127) / 128;
    int loAgg = (Nh + 7) / 8;
    int hiAgg = (N - Nh + 7) / 8;
    int fullAgg = (N + 7) / 8;

    cudaFuncSetAttribute(k_gemm_mma, cudaFuncAttributeMaxDynamicSharedMemorySize, SMEM_GEMM_BYTES);

    static cudaStream_t s2 = nullptr;
    static cudaEvent_t evRoot = nullptr, evCSR = nullptr, evG0 = nullptr, evHi = nullptr;
    if (s2 == nullptr) {
        cudaStreamCreateWithFlags(&s2, cudaStreamNonBlocking);
        cudaEventCreateWithFlags(&evRoot, cudaEventDisableTiming);
        cudaEventCreateWithFlags(&evCSR, cudaEventDisableTiming);
        cudaEventCreateWithFlags(&evG0, cudaEventDisableTiming);
        cudaEventCreateWithFlags(&evHi, cudaEventDisableTiming);
    }

    // fork
    cudaEventRecord(evRoot, 0);
    cudaStreamWaitEvent(s2, evRoot, 0);

    // branch B on s2: fused bucket-CSR build
    k_build<<<CSR_NB, CSR_T, 0, s2>>>(ei, batch, N, E);
    cudaEventRecord(evCSR, s2);

    // branch A on main: W prep + full layer-0 GEMM (fused attention dots)
    k_wprep<<<64, 256>>>(W0, W1);
    k_gemm_mma<<<gemmBlocks, 256, SMEM_GEMM_BYTES>>>(x, 1, 0, a_src0, a_dst0, 0, N);
    cudaEventRecord(evG0, 0);

    // joins for the pipelined middle section
    cudaStreamWaitEvent(0, evCSR, 0);
    cudaStreamWaitEvent(s2, evG0, 0);

    // pipelined halves: agg0 -> gemm1 per node range
    k_agg<<<loAgg, 256>>>(b0, batch, 0, Nh, 1, 0, 1);
    if (hiAgg > 0) k_agg<<<hiAgg, 256, 0, s2>>>(b0, batch, Nh, N, 1, 0, 1);
    k_gemm_mma<<<loTiles, 256, SMEM_GEMM_BYTES>>>(nullptr, 0, 1, a_src1, a_dst1, 0, Nh);
    if (hiTiles > 0)
        k_gemm_mma<<<hiTiles, 256, SMEM_GEMM_BYTES, s2>>>(nullptr, 0, 1, a_src1, a_dst1, Nh, N);
    cudaEventRecord(evHi, s2);
    cudaStreamWaitEvent(0, evHi, 0);

    // layer 1 aggregation (full; g_OUT store skipped) + final division
    k_agg<<<fullAgg, 256>>>(b1, batch, 0, N, 0, 1, 0);
    k_final<<<(2 * G * D + 255) / 256, 256>>>(out);
}